// round 3
// baseline (speedup 1.0000x reference)
#include <cuda_runtime.h>

#define NMAPS   128      // 4*32
#define H       480
#define W       640
#define GRID_N  10
#define CH      48
#define CW      64
#define CELLS   100

// larger value wins; exact tie -> smaller flat index (first occurrence, like jnp.argmax)
__device__ __forceinline__ void combine(float& bv, int& bi, float v, int i) {
    if (v > bv || (v == bv && i < bi)) { bv = v; bi = i; }
}

__global__ __launch_bounds__(1024, 1)
void fused_patchify_kernel(const float* __restrict__ s, float* __restrict__ out, int top_n) {
    const int map  = blockIdx.x;
    const float* mbase = s + (size_t)map * (H * W);
    const int tid  = threadIdx.x;
    const int w    = tid >> 5;
    const int lane = tid & 31;

    __shared__ float pv[CELLS * 3];
    __shared__ int   pi[CELLS * 3];

    // ---- main loop: 30 warps, warp-triple per cell-column, no block barriers ----
    if (w < 30) {
        const int g   = w / 3;        // cell column cj
        const int sub = w - g * 3;    // which 16-row slab of the cell
        const float4* cbase = reinterpret_cast<const float4*>(mbase) + g * (CW / 4); // col offset

        #pragma unroll
        for (int ci = 0; ci < GRID_N; ++ci) {
            const float4* base = cbase + (size_t)(ci * CH) * (W / 4);
            float bv = -3.402823466e38f;
            int   bi = 0x7fffffff;

            // 16 rows per warp: 2 rows per iter (half-warp each), 16 float4 per row
            #pragma unroll
            for (int it = 0; it < 8; ++it) {
                int r = sub * 16 + it * 2 + (lane >> 4);
                int q = lane & 15;
                float4 v = base[r * (W / 4) + q];
                int f = r * CW + q * 4;     // flat idx within cell, row-major
                combine(bv, bi, v.x, f);
                combine(bv, bi, v.y, f + 1);
                combine(bv, bi, v.z, f + 2);
                combine(bv, bi, v.w, f + 3);
            }
            // warp-reduce argmax
            #pragma unroll
            for (int off = 16; off > 0; off >>= 1) {
                float ov = __shfl_down_sync(0xffffffffu, bv, off);
                int   oi = __shfl_down_sync(0xffffffffu, bi, off);
                combine(bv, bi, ov, oi);
            }
            if (lane == 0) {
                int slot = (ci * GRID_N + g) * 3 + sub;   // cell index ci-major, matches reference
                pv[slot] = bv;
                pi[slot] = bi;
            }
        }
    }
    __syncthreads();

    // ---- finalize 100 candidates ----
    __shared__ unsigned long long keys[CELLS];
    __shared__ int   sgr[CELLS], sgc[CELLS];
    __shared__ float ssc[CELLS];

    if (tid < CELLS) {
        const int ci = tid / GRID_N;
        const int cj = tid - ci * GRID_N;
        float bv = pv[tid * 3];
        int   bi = pi[tid * 3];
        combine(bv, bi, pv[tid * 3 + 1], pi[tid * 3 + 1]);
        combine(bv, bi, pv[tid * 3 + 2], pi[tid * 3 + 2]);

        int lr = bi >> 6;           // bi / CW
        int lc = bi & 63;           // bi % CW
        int gr = ci * CH + lr; gr = gr < 1 ? 1 : (gr > H - 2 ? H - 2 : gr);
        int gc = cj * CW + lc; gc = gc < 1 ? 1 : (gc > W - 2 ? W - 2 : gc);

        // score is read at the CLAMPED coordinate (faithful to the reference)
        float sc = mbase[gr * W + gc];
        unsigned u = __float_as_uint(sc);
        unsigned mono = (u & 0x80000000u) ? ~u : (u | 0x80000000u);  // order-preserving map
        keys[tid] = ((unsigned long long)mono << 32) | (unsigned)(CELLS - 1 - tid);
        sgr[tid] = gr; sgc[tid] = gc; ssc[tid] = sc;
    }
    __syncthreads();

    // ---- rank-by-count top-k (jax.lax.top_k semantics) + direct output write ----
    if (tid < CELLS) {
        const unsigned long long mk = keys[tid];
        int rank = 0;
        #pragma unroll 10
        for (int j = 0; j < CELLS; ++j) rank += (keys[j] > mk);
        if (rank < top_n) {
            const int o = map * top_n + rank;
            out[o]                     = (float)sgr[tid];   // x = row indices
            out[NMAPS * top_n + o]     = (float)sgc[tid];   // y = col indices
            out[2 * NMAPS * top_n + o] = ssc[tid];          // scores
        }
    }
}

extern "C" void kernel_launch(void* const* d_in, const int* in_sizes, int n_in,
                              void* d_out, int out_size) {
    const float* s = (const float*)d_in[0];
    int top_n = out_size / (3 * NMAPS);
    fused_patchify_kernel<<<NMAPS, 1024>>>(s, (float*)d_out, top_n);
}

// round 5
// speedup vs baseline: 1.0008x; 1.0008x over previous
#include <cuda_runtime.h>

#define NMAPS   128      // 4*32
#define H       480
#define W       640
#define GRID_N  10
#define CH      48
#define CW      64
#define CELLS   100
#define INTMAX_ 0x7fffffff

__device__ float    g_cand_score[NMAPS * CELLS];
__device__ int      g_cand_gr[NMAPS * CELLS];
__device__ int      g_cand_gc[NMAPS * CELLS];
__device__ unsigned g_count[NMAPS];   // never reset: mod-100 detects last CTA per map per launch

// larger value wins; exact tie -> smaller flat index (first occurrence, like jnp.argmax)
__device__ __forceinline__ void combine(float& bv, int& bi, float v, int i) {
    if (v > bv || (v == bv && i < bi)) { bv = v; bi = i; }
}

__device__ __forceinline__ float vmax4(float4 v) {
    return fmaxf(fmaxf(v.x, v.y), fmaxf(v.z, v.w));
}
// min flat index among components equal to m (independent select tree, no serial chain)
__device__ __forceinline__ int selidx(float4 v, float m, int f) {
    int a = (v.x == m) ? f     : INTMAX_;
    int b = (v.y == m) ? f + 1 : INTMAX_;
    int c = (v.z == m) ? f + 2 : INTMAX_;
    int d = (v.w == m) ? f + 3 : INTMAX_;
    return min(min(a, b), min(c, d));
}

__global__ __launch_bounds__(256)
void cell_argmax_topk_kernel(const float* __restrict__ s, float* __restrict__ out, int top_n) {
    const int cell = blockIdx.x;          // map*CELLS + (ci*GRID_N + cj)
    const int map  = cell / CELLS;
    const int cidx = cell - map * CELLS;
    const int ci   = cidx / GRID_N;
    const int cj   = cidx - ci * GRID_N;

    const float* mbase = s + (size_t)map * (H * W);
    const float4* base = reinterpret_cast<const float4*>(mbase + (size_t)ci * CH * W + cj * CW);

    const int tid = threadIdx.x;
    const int lr  = tid >> 4;             // 16 float4 per 64-float row
    const int lq  = tid & 15;
    const float4* p = base + lr * (W / 4) + lq;

    // 3 independent vector loads up front (MLP=3), rows lr, lr+16, lr+32
    float4 v0 = p[0];
    float4 v1 = p[16 * (W / 4)];
    float4 v2 = p[32 * (W / 4)];

    // independent max tree (depth ~4) instead of serial combine chain
    float tmax = fmaxf(fmaxf(vmax4(v0), vmax4(v1)), vmax4(v2));
    // flat idx: value k of load 'it' sits at (tid + it*256)*4 + k
    int bi = min(min(selidx(v0, tmax, tid * 4),
                     selidx(v1, tmax, tid * 4 + 1024)),
                 selidx(v2, tmax, tid * 4 + 2048));
    float bv = tmax;

    // warp reduce (val, idx)
    #pragma unroll
    for (int off = 16; off > 0; off >>= 1) {
        float ov = __shfl_down_sync(0xffffffffu, bv, off);
        int   oi = __shfl_down_sync(0xffffffffu, bi, off);
        combine(bv, bi, ov, oi);
    }

    __shared__ float sv[8];
    __shared__ int   si[8];
    __shared__ int   s_last;
    const int w = tid >> 5;
    if ((tid & 31) == 0) { sv[w] = bv; si[w] = bi; }
    __syncthreads();

    if (tid == 0) {
        bv = sv[0]; bi = si[0];
        #pragma unroll
        for (int k = 1; k < 8; ++k) combine(bv, bi, sv[k], si[k]);
        int lr2 = bi >> 6;                // bi / CW
        int lc2 = bi & 63;                // bi % CW
        int gr = ci * CH + lr2; gr = gr < 1 ? 1 : (gr > H - 2 ? H - 2 : gr);
        int gc = cj * CW + lc2; gc = gc < 1 ? 1 : (gc > W - 2 ? W - 2 : gc);
        // score is read at the CLAMPED coordinate (faithful to the reference)
        g_cand_score[cell] = mbase[gr * W + gc];
        g_cand_gr[cell]    = gr;
        g_cand_gc[cell]    = gc;
        __threadfence();                  // release: publish candidate before counting
        unsigned old = atomicAdd(&g_count[map], 1u);
        s_last = (old % (unsigned)CELLS) == (unsigned)(CELLS - 1);
    }
    __syncthreads();

    // ---- last CTA of this map performs the per-map top-k ----
    if (s_last) {
        __shared__ unsigned long long keys[CELLS];
        __shared__ int   sgr[CELLS], sgc[CELLS];
        __shared__ float ssc[CELLS];

        __threadfence();                  // acquire: order candidate reads after counter obs
        if (tid < CELLS) {
            float sc = __ldcg(&g_cand_score[map * CELLS + tid]);  // L2, skip stale L1
            int   gr = __ldcg(&g_cand_gr[map * CELLS + tid]);
            int   gc = __ldcg(&g_cand_gc[map * CELLS + tid]);
            unsigned u = __float_as_uint(sc);
            unsigned mono = (u & 0x80000000u) ? ~u : (u | 0x80000000u);
            keys[tid] = ((unsigned long long)mono << 32) | (unsigned)(CELLS - 1 - tid);
            sgr[tid] = gr; sgc[tid] = gc; ssc[tid] = sc;
        }
        __syncthreads();
        if (tid < CELLS) {
            const unsigned long long mk = keys[tid];
            int rank = 0;
            #pragma unroll 10
            for (int j = 0; j < CELLS; ++j) rank += (keys[j] > mk);
            if (rank < top_n) {
                const int o = map * top_n + rank;
                out[o]                     = (float)sgr[tid];   // x = row indices
                out[NMAPS * top_n + o]     = (float)sgc[tid];   // y = col indices
                out[2 * NMAPS * top_n + o] = ssc[tid];          // scores
            }
        }
    }
}

extern "C" void kernel_launch(void* const* d_in, const int* in_sizes, int n_in,
                              void* d_out, int out_size) {
    const float* s = (const float*)d_in[0];
    int top_n = out_size / (3 * NMAPS);
    cell_argmax_topk_kernel<<<NMAPS * CELLS, 256>>>(s, (float*)d_out, top_n);
}

// round 8
// speedup vs baseline: 1.0974x; 1.0965x over previous
#include <cuda_runtime.h>

#define NMAPS   128      // 4*32
#define H       480
#define W       640
#define GRID_N  10
#define CH      48
#define CW      64
#define CELLS   100
#define INTMAX_ 0x7fffffff

__device__ float    g_cand_score[NMAPS * CELLS];
__device__ int      g_cand_gr[NMAPS * CELLS];
__device__ int      g_cand_gc[NMAPS * CELLS];
__device__ unsigned g_count[NMAPS];   // never reset: mod-100 detects last arrival per map per launch

// larger value wins; exact tie -> smaller flat index (first occurrence, like jnp.argmax)
__device__ __forceinline__ void combine(float& bv, int& bi, float v, int i) {
    if (v > bv || (v == bv && i < bi)) { bv = v; bi = i; }
}
__device__ __forceinline__ float vmax4(float4 v) {
    return fmaxf(fmaxf(v.x, v.y), fmaxf(v.z, v.w));
}
__device__ __forceinline__ int selidx(float4 v, float m, int f) {
    int a = (v.x == m) ? f     : INTMAX_;
    int b = (v.y == m) ? f + 1 : INTMAX_;
    int c = (v.z == m) ? f + 2 : INTMAX_;
    int d = (v.w == m) ? f + 3 : INTMAX_;
    return min(min(a, b), min(c, d));
}

// One CTA covers TWO horizontally adjacent cells: 48 rows x 128 cols contiguous.
// grid = NMAPS * GRID_N * (GRID_N/2) = 6400, block = 256.
__global__ __launch_bounds__(256)
void dualcell_argmax_topk_kernel(const float* __restrict__ s, float* __restrict__ out, int top_n) {
    const int blk  = blockIdx.x;                 // map*50 + ci*5 + j
    const int map  = blk / 50;
    const int rem  = blk - map * 50;
    const int ci   = rem / 5;
    const int j    = rem - ci * 5;               // double-cell column, covers cj=2j,2j+1

    const float* mbase = s + (size_t)map * (H * W);
    const float4* base4 = reinterpret_cast<const float4*>(mbase)
                        + (size_t)(ci * CH) * (W / 4) + j * 32;   // 128 floats = 32 float4

    const int tid = threadIdx.x;
    const int lr  = tid >> 5;      // warp id = starting row (warp covers one 512B row)
    const int lq  = tid & 31;      // float4 within 128-col double row
    const int half = lq >> 4;      // 0 -> cell 2j, 1 -> cell 2j+1
    const int ccol = lq & 15;      // float4 col within the cell

    const float4* p = base4 + lr * (W / 4) + lq;
    const int rowstep = 8 * (W / 4);

    // 6 independent 16B loads (rows lr, lr+8, ..., lr+40) -> MLP=6 per thread
    float4 v0 = p[0];
    float4 v1 = p[rowstep];
    float4 v2 = p[2 * rowstep];
    float4 v3 = p[3 * rowstep];
    float4 v4 = p[4 * rowstep];
    float4 v5 = p[5 * rowstep];

    float tmax = fmaxf(fmaxf(fmaxf(vmax4(v0), vmax4(v1)), fmaxf(vmax4(v2), vmax4(v3))),
                       fmaxf(vmax4(v4), vmax4(v5)));
    // flat idx within the thread's cell: (lr + 8*it)*64 + ccol*4 + k
    const int fb = lr * 64 + ccol * 4;
    int bi = min(min(min(selidx(v0, tmax, fb),
                         selidx(v1, tmax, fb + 8 * 64)),
                     min(selidx(v2, tmax, fb + 16 * 64),
                         selidx(v3, tmax, fb + 24 * 64))),
                 min(selidx(v4, tmax, fb + 32 * 64),
                     selidx(v5, tmax, fb + 40 * 64)));
    float bv = tmax;

    // half-warp (width 16) reduce: lanes 0 and 16 end with per-cell partials
    #pragma unroll
    for (int off = 8; off > 0; off >>= 1) {
        float ov = __shfl_down_sync(0xffffffffu, bv, off, 16);
        int   oi = __shfl_down_sync(0xffffffffu, bi, off, 16);
        combine(bv, bi, ov, oi);
    }

    __shared__ float sv[2][8];
    __shared__ int   si[2][8];
    __shared__ int   s_last;
    if (tid == 0) s_last = 0;
    if ((lq & 15) == 0) { sv[half][lr] = bv; si[half][lr] = bi; }
    __syncthreads();

    // threads 0 and 1 finalize the two cells
    if (tid < 2) {
        float fv = sv[tid][0];
        int   fi = si[tid][0];
        #pragma unroll
        for (int k = 1; k < 8; ++k) combine(fv, fi, sv[tid][k], si[tid][k]);
        const int cj   = 2 * j + tid;
        const int cidx = ci * GRID_N + cj;
        int lr2 = fi >> 6;
        int lc2 = fi & 63;
        int gr = ci * CH + lr2; gr = gr < 1 ? 1 : (gr > H - 2 ? H - 2 : gr);
        int gc = cj * CW + lc2; gc = gc < 1 ? 1 : (gc > W - 2 ? W - 2 : gc);
        // score is read at the CLAMPED coordinate (faithful to the reference)
        const int cell = map * CELLS + cidx;
        g_cand_score[cell] = mbase[gr * W + gc];
        g_cand_gr[cell]    = gr;
        g_cand_gc[cell]    = gc;
        __threadfence();                       // release: publish before counting
        unsigned old = atomicAdd(&g_count[map], 1u);
        if ((old % (unsigned)CELLS) == (unsigned)(CELLS - 1)) s_last = 1;
    }
    __syncthreads();

    // ---- the CTA that published the map's 100th candidate does the top-k ----
    if (s_last) {
        __shared__ unsigned long long keys[CELLS];
        __shared__ int   sgr[CELLS], sgc[CELLS];
        __shared__ float ssc[CELLS];

        __threadfence();                       // acquire
        if (tid < CELLS) {
            float sc = __ldcg(&g_cand_score[map * CELLS + tid]);
            int   gr = __ldcg(&g_cand_gr[map * CELLS + tid]);
            int   gc = __ldcg(&g_cand_gc[map * CELLS + tid]);
            unsigned u = __float_as_uint(sc);
            unsigned mono = (u & 0x80000000u) ? ~u : (u | 0x80000000u);
            keys[tid] = ((unsigned long long)mono << 32) | (unsigned)(CELLS - 1 - tid);
            sgr[tid] = gr; sgc[tid] = gc; ssc[tid] = sc;
        }
        __syncthreads();
        if (tid < CELLS) {
            const unsigned long long mk = keys[tid];
            int rank = 0;
            #pragma unroll 10
            for (int jj = 0; jj < CELLS; ++jj) rank += (keys[jj] > mk);
            if (rank < top_n) {
                const int o = map * top_n + rank;
                out[o]                     = (float)sgr[tid];   // x = row indices
                out[NMAPS * top_n + o]     = (float)sgc[tid];   // y = col indices
                out[2 * NMAPS * top_n + o] = ssc[tid];          // scores
            }
        }
    }
}

extern "C" void kernel_launch(void* const* d_in, const int* in_sizes, int n_in,
                              void* d_out, int out_size) {
    const float* s = (const float*)d_in[0];
    int top_n = out_size / (3 * NMAPS);
    dualcell_argmax_topk_kernel<<<NMAPS * GRID_N * (GRID_N / 2), 256>>>(s, (float*)d_out, top_n);
}